// round 15
// baseline (speedup 1.0000x reference)
#include <cuda_runtime.h>
#include <cuda_bf16.h>
#include <math.h>

#define Nn   10000
#define Ee   100000

__device__ float    g_msg[Ee * 80];
__device__ float    g_logit[Ee];
__device__ float    g_ex[Ee];
__device__ unsigned g_max[Nn];
__device__ float    g_den[Nn];
__device__ float    g_agg[Nn * 80];
__device__ float    g_x[Nn * 80];
__device__ float    g_stats[80];
__device__ float    g_norm[80];
// W2 pre-split into bf16 hi/lo, TRANSPOSED to [col][k] (col=0..2559, k=0..63)
__device__ __nv_bfloat16 g_w2hi[2560 * 64];
__device__ __nv_bfloat16 g_w2lo[2560 * 64];

__device__ __forceinline__ unsigned fenc(float f) {
    unsigned b = __float_as_uint(f);
    return (b & 0x80000000u) ? ~b : (b | 0x80000000u);
}
__device__ __forceinline__ float fdec(unsigned u) {
    return (u & 0x80000000u) ? __uint_as_float(u & 0x7fffffffu) : __uint_as_float(~u);
}
__device__ __forceinline__ float warpsum(float v) {
    #pragma unroll
    for (int o = 16; o; o >>= 1) v += __shfl_xor_sync(0xffffffffu, v, o);
    return v;
}
__device__ __forceinline__ void mma_bf16(float* d, const unsigned* a, const unsigned* b) {
    asm volatile(
        "mma.sync.aligned.m16n8k16.row.col.f32.bf16.bf16.f32 "
        "{%0,%1,%2,%3}, {%4,%5,%6,%7}, {%8,%9}, {%0,%1,%2,%3};\n"
        : "+f"(d[0]), "+f"(d[1]), "+f"(d[2]), "+f"(d[3])
        : "r"(a[0]), "r"(a[1]), "r"(a[2]), "r"(a[3]), "r"(b[0]), "r"(b[1]));
}
__device__ __forceinline__ void ldsm4(unsigned* r, unsigned addr) {
    asm volatile("ldmatrix.sync.aligned.m8n8.x4.shared.b16 {%0,%1,%2,%3}, [%4];\n"
        : "=r"(r[0]), "=r"(r[1]), "=r"(r[2]), "=r"(r[3]) : "r"(addr));
}

__global__ void k_init() {
    int i = blockIdx.x * blockDim.x + threadIdx.x;
    int st = gridDim.x * blockDim.x;
    for (int x = i; x < Nn * 80; x += st) g_agg[x] = 0.f;
    for (int x = i; x < Nn; x += st) { g_den[x] = 0.f; g_max[x] = 0u; }
    if (i < 80) g_stats[i] = 0.f;
}

// split + transpose W2 (coalesced both sides via smem tile)
__global__ void __launch_bounds__(256) k_prep(const float* __restrict__ W2) {
    __shared__ float tile[64][65];
    int c0 = blockIdx.x * 64;
    int tid = threadIdx.x;
    for (int i = tid; i < 4096; i += 256) {
        int r = i >> 6, c = i & 63;
        tile[r][c] = W2[r * 2560 + c0 + c];
    }
    __syncthreads();
    for (int i = tid; i < 4096; i += 256) {
        int c = i >> 6, r = i & 63;
        float x = tile[r][c];
        __nv_bfloat16 hi = __float2bfloat16(x);
        g_w2hi[(c0 + c) * 64 + r] = hi;
        g_w2lo[(c0 + c) * 64 + r] = __float2bfloat16(x - __bfloat162float(hi));
    }
}

// ------------- smem layout (float offsets) -------------
#define SM_AH   0        // h hi bf16 [32 rows][72 halves] = 1152 floats
#define SM_AL   1152     // h lo
#define SM_BH   2304     // W2 chunk hi bf16 [128 cols][72 halves] = 4608 floats
#define SM_BL   6912     // W2 chunk lo
#define SM_TP   11520    // tp tile fp32 [32][136]
#define SM_U    15872    // per-edge u vectors [32][184]
#define SM_ACC  21760    // msg accumulators [32][84]
#define SM_SH   24448
#define SM_ENV  24576
#define SM_IDX  24608
#define SM_TOT  24672
#define SMEM_BYTES (SM_TOT * 4)
#define UA    0
#define UDOT  32
#define US    48
#define UVY0  80
#define UCRS  128
#define UY1   176
#define USTR  184

__global__ void __launch_bounds__(256, 2) k_edge(
    const float* __restrict__ nf, const int* __restrict__ ei,
    const float* __restrict__ sh, const float* __restrict__ radial,
    const float* __restrict__ env,
    const float* __restrict__ W1, const float* __restrict__ b1,
    const float* __restrict__ b2,
    const float* __restrict__ Wq, const float* __restrict__ bq,
    const float* __restrict__ Wk, const float* __restrict__ bk)
{
    extern __shared__ float sm[];
    const int tid = threadIdx.x;
    const int e0  = blockIdx.x * 32;
    int* isrc = (int*)&sm[SM_IDX];
    int* idst = isrc + 32;
    __nv_bfloat16* hAhi = (__nv_bfloat16*)(sm + SM_AH);
    __nv_bfloat16* hAlo = (__nv_bfloat16*)(sm + SM_AL);
    __nv_bfloat16* wBhi = (__nv_bfloat16*)(sm + SM_BH);
    __nv_bfloat16* wBlo = (__nv_bfloat16*)(sm + SM_BL);

    if (tid < 32) {
        isrc[tid] = ei[e0 + tid];
        idst[tid] = ei[Ee + e0 + tid];
        sm[SM_ENV + tid] = env[e0 + tid];
    }
    if (tid < 128) sm[SM_SH + tid] = sh[e0 * 4 + tid];
    // stage radial into SM_BH scratch [e][17]
    for (int idx = tid; idx < 512; idx += 256) {
        int e = idx >> 4, j = idx & 15;
        sm[SM_BH + e * 17 + j] = radial[(e0 + e) * 16 + j];
    }
    __syncthreads();

    // gather source node features: s_src -> U, v_src -> TP scratch
    for (int idx = tid; idx < 32 * 80; idx += 256) {
        int e = idx / 80, f = idx - e * 80;
        float v = __ldg(&nf[isrc[e] * 80 + f]);
        if (f < 32) sm[SM_U + e * USTR + US + f] = v;
        else        sm[SM_TP + e * 48 + (f - 32)] = v;
    }
    __syncthreads();

    // h = silu(radial @ W1 + b1), split to bf16 hi/lo, layout [e][72]
    {
        int e = tid & 31, r0 = tid >> 5;
        float rr[16];
        #pragma unroll
        for (int j = 0; j < 16; j++) rr[j] = sm[SM_BH + e * 17 + j];
        #pragma unroll
        for (int u = 0; u < 8; u++) {
            int r = r0 + u * 8;
            float x = __ldg(&b1[r]);
            #pragma unroll
            for (int j = 0; j < 16; j++) x += rr[j] * __ldg(&W1[j * 64 + r]);
            x = x / (1.f + expf(-x));
            __nv_bfloat16 hi = __float2bfloat16(x);
            hAhi[e * 72 + r] = hi;
            hAlo[e * 72 + r] = __float2bfloat16(x - __bfloat162float(hi));
        }
    }
    for (int idx = tid; idx < 32 * 84; idx += 256) sm[SM_ACC + idx] = 0.f;
    __syncthreads();

    // per-edge u vectors
    if (tid < 32) {
        int e = tid;
        float y0  = sm[SM_SH + e * 4 + 0];
        float y1x = sm[SM_SH + e * 4 + 1];
        float y1y = sm[SM_SH + e * 4 + 2];
        float y1z = sm[SM_SH + e * 4 + 3];
        float* U = &sm[SM_U + e * USTR];
        #pragma unroll
        for (int s = 0; s < 32; s++) U[UA + s] = U[US + s] * y0;
        const float is3 = 0.57735026918962576f, is2 = 0.70710678118654752f;
        #pragma unroll
        for (int v = 0; v < 16; v++) {
            float a = sm[SM_TP + e * 48 + v * 3 + 0];
            float b = sm[SM_TP + e * 48 + v * 3 + 1];
            float c = sm[SM_TP + e * 48 + v * 3 + 2];
            U[UDOT + v] = (a * y1x + b * y1y + c * y1z) * is3;
            U[UVY0 + v * 3 + 0] = a * y0;
            U[UVY0 + v * 3 + 1] = b * y0;
            U[UVY0 + v * 3 + 2] = c * y0;
            U[UCRS + v * 3 + 0] = (b * y1z - c * y1y) * is2;
            U[UCRS + v * 3 + 1] = (c * y1x - a * y1z) * is2;
            U[UCRS + v * 3 + 2] = (a * y1y - b * y1x) * is2;
        }
        U[UY1 + 0] = y1x; U[UY1 + 1] = y1y; U[UY1 + 2] = y1z;
    }

    // tensor-core GEMM (32 edges x 2560 cols, K=64) fused with contraction
    const int lane = tid & 31, w = tid >> 5;
    const int mt = w & 1, ng = w >> 1;       // warp: m-tile (16 edges), 32-col group
    const int g  = lane >> 2, tg = lane & 3;

    // ldmatrix addresses: tile index at = lane>>3, row-in-tile ar = lane&7
    const int at = lane >> 3, ar = lane & 7;
    const unsigned aAh = (unsigned)__cvta_generic_to_shared(
        &hAhi[(mt * 16 + (at & 1) * 8 + ar) * 72 + (at >> 1) * 8]);
    const unsigned aAl = aAh + (SM_AL - SM_AH) * 4;
    const unsigned aB0h = (unsigned)__cvta_generic_to_shared(
        &wBhi[(ng * 32 + (at >> 1) * 8 + ar) * 72 + (at & 1) * 8]);
    const unsigned aB1h = aB0h + 16 * 72 * 2;
    const unsigned aB0l = aB0h + (SM_BL - SM_BH) * 4;
    const unsigned aB1l = aB0l + 16 * 72 * 2;

    // register prefetch of chunk 0
    uint4 pf[8];
    #pragma unroll
    for (int j = 0; j < 8; j++) {
        int idx = tid + j * 256;
        int arr = idx >> 10, rem = idx & 1023, n = rem >> 3, seg = (rem & 7) << 3;
        const __nv_bfloat16* s = (arr ? g_w2lo : g_w2hi) + n * 64 + seg;
        pf[j] = *(const uint4*)s;
    }
    __syncthreads();   // covers u-vector phase too

    for (int ch = 0; ch < 20; ch++) {
        const int c0 = ch * 128;
        // store prefetched chunk into B smem
        #pragma unroll
        for (int j = 0; j < 8; j++) {
            int idx = tid + j * 256;
            int arr = idx >> 10, rem = idx & 1023, n = rem >> 3, seg = (rem & 7) << 3;
            __nv_bfloat16* dst = (arr ? wBlo : wBhi) + n * 72 + seg;
            *(uint4*)dst = pf[j];
        }
        __syncthreads();
        // prefetch next chunk (overlaps MMA + contraction)
        if (ch < 19) {
            #pragma unroll
            for (int j = 0; j < 8; j++) {
                int idx = tid + j * 256;
                int arr = idx >> 10, rem = idx & 1023, n = rem >> 3, seg = (rem & 7) << 3;
                const __nv_bfloat16* s = (arr ? g_w2lo : g_w2hi) + ((ch + 1) * 128 + n) * 64 + seg;
                pf[j] = *(const uint4*)s;
            }
        }

        float acc[4][4];
        #pragma unroll
        for (int nt = 0; nt < 4; nt++)
            #pragma unroll
            for (int i = 0; i < 4; i++) acc[nt][i] = 0.f;

        #pragma unroll
        for (int kt = 0; kt < 4; kt++) {
            const unsigned off = kt * 32;   // 16 halves = 32 bytes
            unsigned ah[4], al[4], b0h[4], b1h[4], b0l[4], b1l[4];
            ldsm4(ah, aAh + off);
            ldsm4(al, aAl + off);
            ldsm4(b0h, aB0h + off);
            ldsm4(b1h, aB1h + off);
            ldsm4(b0l, aB0l + off);
            ldsm4(b1l, aB1l + off);
            mma_bf16(acc[0], ah, b0h + 0); mma_bf16(acc[1], ah, b0h + 2);
            mma_bf16(acc[2], ah, b1h + 0); mma_bf16(acc[3], ah, b1h + 2);
            mma_bf16(acc[0], ah, b0l + 0); mma_bf16(acc[1], ah, b0l + 2);
            mma_bf16(acc[2], ah, b1l + 0); mma_bf16(acc[3], ah, b1l + 2);
            mma_bf16(acc[0], al, b0h + 0); mma_bf16(acc[1], al, b0h + 2);
            mma_bf16(acc[2], al, b1h + 0); mma_bf16(acc[3], al, b1h + 2);
        }

        // store tp tile (+bias)
        #pragma unroll
        for (int nt = 0; nt < 4; nt++) {
            const int col = ng * 32 + nt * 8 + tg * 2;
            const float bx = __ldg(&b2[c0 + col]);
            const float by = __ldg(&b2[c0 + col + 1]);
            const int r0 = mt * 16 + g;
            float2 v0 = { acc[nt][0] + bx, acc[nt][1] + by };
            float2 v1 = { acc[nt][2] + bx, acc[nt][3] + by };
            *(float2*)&sm[SM_TP + r0 * 136 + col] = v0;
            *(float2*)&sm[SM_TP + (r0 + 8) * 136 + col] = v1;
        }
        __syncthreads();

        // contraction of this chunk into message accumulators
        if (ch < 12) {  // WA (s-major) or WB (v-major), 32 outputs
            int uoff = (ch < 8) ? (UA + ch * 4) : (UDOT + (ch - 8) * 4);
            int k = tid & 31, eb = tid >> 5;
            #pragma unroll
            for (int jj = 0; jj < 4; jj++) {
                int e = eb + jj * 8;
                const float* t = &sm[SM_TP + e * 136];
                const float* U = &sm[SM_U + e * USTR + uoff];
                sm[SM_ACC + e * 84 + k] +=
                    t[k] * U[0] + t[32 + k] * U[1] + t[64 + k] * U[2] + t[96 + k] * U[3];
            }
        } else {        // WC / WD / WE, 16 vector outputs x 3 components
            int k = tid & 15, eb = tid >> 4;
            #pragma unroll
            for (int jj = 0; jj < 2; jj++) {
                int e = eb + jj * 16;
                const float* t = &sm[SM_TP + e * 136];
                const float* U = &sm[SM_U + e * USTR];
                float* A = &sm[SM_ACC + e * 84 + 32 + k * 3];
                if (ch < 16) {
                    int i0 = US + (ch - 12) * 8;
                    float tC = 0.f;
                    #pragma unroll
                    for (int i = 0; i < 8; i++) tC += t[i * 16 + k] * U[i0 + i];
                    A[0] += tC * U[UY1 + 0];
                    A[1] += tC * U[UY1 + 1];
                    A[2] += tC * U[UY1 + 2];
                } else {
                    int ub = (ch < 18) ? (UVY0 + (ch - 16) * 24) : (UCRS + (ch - 18) * 24);
                    float s0 = 0.f, s1 = 0.f, s2 = 0.f;
                    #pragma unroll
                    for (int i = 0; i < 8; i++) {
                        float tv = t[i * 16 + k];
                        s0 += tv * U[ub + i * 3 + 0];
                        s1 += tv * U[ub + i * 3 + 1];
                        s2 += tv * U[ub + i * 3 + 2];
                    }
                    A[0] += s0; A[1] += s1; A[2] += s2;
                }
            }
        }
        __syncthreads();
    }

    // scale + write messages; gather dst scalars for q (SM_BH scratch)
    const float A0c = 0.14433756729740643f;  // 1/sqrt(48)
    const float A1c = 0.125f;                // 1/sqrt(64)
    for (int idx = tid; idx < 2560; idx += 256) {
        int e = idx / 80, f = idx - e * 80;
        float m = sm[SM_ACC + e * 84 + f] * (f < 32 ? A0c : A1c);
        sm[SM_ACC + e * 84 + f] = m;
        g_msg[(e0 + e) * 80 + f] = m;
    }
    for (int idx = tid; idx < 1024; idx += 256) {
        int e = idx >> 5, f = idx & 31;
        sm[SM_BH + e * 33 + f] = __ldg(&nf[idst[e] * 80 + f]);
    }
    __syncthreads();
    {
        int e = tid >> 3, j = tid & 7;
        float kh = __ldg(&bk[j]), qh = __ldg(&bq[j]);
        #pragma unroll
        for (int k = 0; k < 32; k++) {
            kh += sm[SM_ACC + e * 84 + k] * __ldg(&Wk[k * 8 + j]);
            qh += sm[SM_BH + e * 33 + k] * __ldg(&Wq[k * 8 + j]);
        }
        float p = kh * qh;
        p += __shfl_down_sync(0xffffffffu, p, 4, 8);
        p += __shfl_down_sync(0xffffffffu, p, 2, 8);
        p += __shfl_down_sync(0xffffffffu, p, 1, 8);
        if (j == 0) {
            float lg = p * 0.35355339059327373f + logf(sm[SM_ENV + e] + 1e-8f);
            g_logit[e0 + e] = lg;
            atomicMax(&g_max[idst[e]], fenc(lg));
        }
    }
}

__global__ void k_soft(const int* __restrict__ ei) {
    int e = blockIdx.x * blockDim.x + threadIdx.x;
    if (e >= Ee) return;
    int dst = ei[Ee + e];
    float ex = expf(g_logit[e] - fdec(g_max[dst]));
    g_ex[e] = ex;
    atomicAdd(&g_den[dst], ex);
}

__global__ void k_agg(const int* __restrict__ ei) {
    int idx = blockIdx.x * blockDim.x + threadIdx.x;
    if (idx >= Ee * 80) return;
    unsigned e = (unsigned)idx / 80u;
    int f = idx - (int)e * 80;
    int dst = ei[Ee + e];
    float attn = g_ex[e] / (g_den[dst] + 1e-8f);
    atomicAdd(&g_agg[dst * 80 + f], attn * g_msg[idx]);
}

__global__ void __launch_bounds__(256) k_node(
    const float* __restrict__ nf,
    const float* __restrict__ Wout_s, const float* __restrict__ Wout_v,
    const float* __restrict__ Wg_s,   const float* __restrict__ Wg_v)
{
    __shared__ float ws[1024], wgs[1536], wv[256], wgv[256], st[80];
    int tid = threadIdx.x;
    for (int i = tid; i < 1024; i += 256) ws[i] = Wout_s[i];
    for (int i = tid; i < 1536; i += 256) wgs[i] = Wg_s[i];
    wv[tid]  = Wout_v[tid];
    wgv[tid] = Wg_v[tid];
    if (tid < 80) st[tid] = 0.f;
    __syncthreads();

    int n = blockIdx.x * 256 + tid;
    bool act = (n < Nn);
    const float isS = 0.17677669529663687f;
    int lane = tid & 31;

    float xs[32], gsig[16];
    if (act) {
        float as[32], a2[32], gsv[48];
        #pragma unroll
        for (int s = 0; s < 32; s++) as[s] = g_agg[n * 80 + s];
        #pragma unroll
        for (int k = 0; k < 32; k++) {
            float a = 0.f;
            #pragma unroll
            for (int s = 0; s < 32; s++) a += as[s] * ws[s * 32 + k];
            a2[k] = a * isS;
        }
        #pragma unroll
        for (int j = 0; j < 48; j++) {
            float a = 0.f;
            #pragma unroll
            for (int s = 0; s < 32; s++) a += a2[s] * wgs[s * 48 + j];
            gsv[j] = a * isS;
        }
        #pragma unroll
        for (int k = 0; k < 32; k++) {
            float v = gsv[k];
            xs[k] = v / (1.f + expf(-v)) + nf[n * 80 + k];
        }
        #pragma unroll
        for (int k = 0; k < 16; k++) gsig[k] = 1.f / (1.f + expf(-gsv[32 + k]));
    } else {
        #pragma unroll
        for (int k = 0; k < 32; k++) xs[k] = 0.f;
        #pragma unroll
        for (int k = 0; k < 16; k++) gsig[k] = 0.f;
    }
    #pragma unroll
    for (int k = 0; k < 32; k++) {
        if (act) g_x[n * 80 + k] = xs[k];
        float s1 = warpsum(xs[k]);
        float s2 = warpsum(xs[k] * xs[k]);
        if (lane == 0) { atomicAdd(&st[k], s1); atomicAdd(&st[32 + k], s2); }
    }

    float vsum[16];
    #pragma unroll
    for (int w = 0; w < 16; w++) vsum[w] = 0.f;
    for (int c = 0; c < 3; c++) {
        float xv[16];
        if (act) {
            float av[16], a2v[16];
            #pragma unroll
            for (int v = 0; v < 16; v++) av[v] = g_agg[n * 80 + 32 + v * 3 + c];
            #pragma unroll
            for (int w = 0; w < 16; w++) {
                float a = 0.f;
                #pragma unroll
                for (int v = 0; v < 16; v++) a += av[v] * wv[v * 16 + w];
                a2v[w] = a * 0.25f;
            }
            #pragma unroll
            for (int w = 0; w < 16; w++) {
                float a = 0.f;
                #pragma unroll
                for (int v = 0; v < 16; v++) a += a2v[v] * wgv[v * 16 + w];
                float x = gsig[w] * (a * 0.25f) + nf[n * 80 + 32 + w * 3 + c];
                xv[w] = x;
                g_x[n * 80 + 32 + w * 3 + c] = x;
            }
        } else {
            #pragma unroll
            for (int w = 0; w < 16; w++) xv[w] = 0.f;
        }
        #pragma unroll
        for (int w = 0; w < 16; w++) vsum[w] += xv[w] * xv[w];
    }
    #pragma unroll
    for (int w = 0; w < 16; w++) {
        float s = warpsum(vsum[w]);
        if (lane == 0) atomicAdd(&st[64 + w], s);
    }
    __syncthreads();
    if (tid < 80) atomicAdd(&g_stats[tid], st[tid]);
}

__global__ void k_stats(const float* __restrict__ bn_ws,
                        const float* __restrict__ bn_bs,
                        const float* __restrict__ bn_wv) {
    int i = threadIdx.x;
    if (i < 32) {
        float mean = g_stats[i] / (float)Nn;
        float var  = g_stats[32 + i] / (float)Nn - mean * mean;
        float sc   = bn_ws[i] / sqrtf(var + 1e-5f);
        g_norm[i]      = sc;
        g_norm[32 + i] = bn_bs[i] - mean * sc;
    } else if (i < 48) {
        int v = i - 32;
        float vn = g_stats[64 + v] / (3.f * (float)Nn);
        g_norm[64 + v] = bn_wv[v] / sqrtf(vn + 1e-5f);
    }
}

__global__ void k_out(float* __restrict__ out) {
    int idx = blockIdx.x * blockDim.x + threadIdx.x;
    if (idx >= Nn * 80) return;
    int f = idx % 80;
    float x = g_x[idx];
    if (f < 32) out[idx] = x * g_norm[f] + g_norm[32 + f];
    else        out[idx] = x * g_norm[64 + (f - 32) / 3];
}

extern "C" void kernel_launch(void* const* d_in, const int* in_sizes, int n_in,
                              void* d_out, int out_size) {
    const float* nf     = (const float*)d_in[0];
    const int*   ei     = (const int*)  d_in[1];
    const float* sh     = (const float*)d_in[2];
    const float* radial = (const float*)d_in[3];
    const float* env    = (const float*)d_in[4];
    const float* W1     = (const float*)d_in[5];
    const float* b1     = (const float*)d_in[6];
    const float* W2     = (const float*)d_in[7];
    const float* b2     = (const float*)d_in[8];
    const float* Wq     = (const float*)d_in[9];
    const float* bq     = (const float*)d_in[10];
    const float* Wk     = (const float*)d_in[11];
    const float* bk     = (const float*)d_in[12];
    const float* Wout_s = (const float*)d_in[13];
    const float* Wout_v = (const float*)d_in[14];
    const float* Wg_s   = (const float*)d_in[15];
    const float* Wg_v   = (const float*)d_in[16];
    const float* bn_ws  = (const float*)d_in[17];
    const float* bn_bs  = (const float*)d_in[18];
    const float* bn_wv  = (const float*)d_in[19];
    float* out = (float*)d_out;

    cudaFuncSetAttribute(k_edge, cudaFuncAttributeMaxDynamicSharedMemorySize, SMEM_BYTES);

    k_init<<<1024, 256>>>();
    k_prep<<<40, 256>>>(W2);
    k_edge<<<Ee / 32, 256, SMEM_BYTES>>>(nf, ei, sh, radial, env,
                                         W1, b1, b2, Wq, bq, Wk, bk);
    k_soft<<<(Ee + 255) / 256, 256>>>(ei);
    k_agg<<<(Ee * 80 + 255) / 256, 256>>>(ei);
    k_node<<<(Nn + 255) / 256, 256>>>(nf, Wout_s, Wout_v, Wg_s, Wg_v);
    k_stats<<<1, 64>>>(bn_ws, bn_bs, bn_wv);
    k_out<<<(Nn * 80 + 255) / 256, 256>>>(out);
}

// round 16
// speedup vs baseline: 1.6057x; 1.6057x over previous
#include <cuda_runtime.h>
#include <cuda_bf16.h>
#include <math.h>

#define Nn   10000
#define Ee   100000

__device__ float    g_msg[Ee * 80];
__device__ float    g_logit[Ee];
__device__ float    g_ex[Ee];
__device__ unsigned g_max[Nn];
__device__ float    g_den[Nn];
__device__ float    g_agg[Nn * 80];
__device__ float    g_x[Nn * 80];
__device__ float    g_stats[80];
__device__ float    g_norm[80];
// W2 pre-split into bf16 hi/lo, TRANSPOSED to [col][k] (col=0..2559, k=0..63)
__device__ __nv_bfloat16 g_w2hi[2560 * 64];
__device__ __nv_bfloat16 g_w2lo[2560 * 64];

__device__ __forceinline__ unsigned fenc(float f) {
    unsigned b = __float_as_uint(f);
    return (b & 0x80000000u) ? ~b : (b | 0x80000000u);
}
__device__ __forceinline__ float fdec(unsigned u) {
    return (u & 0x80000000u) ? __uint_as_float(u & 0x7fffffffu) : __uint_as_float(~u);
}
__device__ __forceinline__ float warpsum(float v) {
    #pragma unroll
    for (int o = 16; o; o >>= 1) v += __shfl_xor_sync(0xffffffffu, v, o);
    return v;
}
__device__ __forceinline__ void mma_bf16(float* d, const unsigned* a, const unsigned* b) {
    asm volatile(
        "mma.sync.aligned.m16n8k16.row.col.f32.bf16.bf16.f32 "
        "{%0,%1,%2,%3}, {%4,%5,%6,%7}, {%8,%9}, {%0,%1,%2,%3};\n"
        : "+f"(d[0]), "+f"(d[1]), "+f"(d[2]), "+f"(d[3])
        : "r"(a[0]), "r"(a[1]), "r"(a[2]), "r"(a[3]), "r"(b[0]), "r"(b[1]));
}
__device__ __forceinline__ void ldsm4(unsigned* r, unsigned addr) {
    asm volatile("ldmatrix.sync.aligned.m8n8.x4.shared.b16 {%0,%1,%2,%3}, [%4];\n"
        : "=r"(r[0]), "=r"(r[1]), "=r"(r[2]), "=r"(r[3]) : "r"(addr));
}
__device__ __forceinline__ void cpasync16(unsigned s, const void* g) {
    asm volatile("cp.async.cg.shared.global [%0], [%1], 16;\n" :: "r"(s), "l"(g));
}

__global__ void k_init() {
    int i = blockIdx.x * blockDim.x + threadIdx.x;
    int st = gridDim.x * blockDim.x;
    for (int x = i; x < Nn * 80; x += st) g_agg[x] = 0.f;
    for (int x = i; x < Nn; x += st) { g_den[x] = 0.f; g_max[x] = 0u; }
    if (i < 80) g_stats[i] = 0.f;
}

// split + transpose W2 (coalesced both sides via smem tile)
__global__ void __launch_bounds__(256) k_prep(const float* __restrict__ W2) {
    __shared__ float tile[64][65];
    int c0 = blockIdx.x * 64;
    int tid = threadIdx.x;
    for (int i = tid; i < 4096; i += 256) {
        int r = i >> 6, c = i & 63;
        tile[r][c] = W2[r * 2560 + c0 + c];
    }
    __syncthreads();
    for (int i = tid; i < 4096; i += 256) {
        int c = i >> 6, r = i & 63;
        float x = tile[r][c];
        __nv_bfloat16 hi = __float2bfloat16(x);
        g_w2hi[(c0 + c) * 64 + r] = hi;
        g_w2lo[(c0 + c) * 64 + r] = __float2bfloat16(x - __bfloat162float(hi));
    }
}

// ------------- smem layout (float offsets) -------------
#define SM_AH   0        // h hi bf16 [32 rows][72 halves] = 1152 floats
#define SM_AL   1152     // h lo
#define SM_BH   2304     // W2 chunk hi bf16 [128 cols][72 halves] = 4608 floats
#define SM_BL   6912     // W2 chunk lo
#define SM_TP   11520    // tp tile fp32 [32][136]
#define SM_U    15872    // per-edge u vectors [32][184]
#define SM_ACC  21760    // msg accumulators [32][84]
#define SM_SH   24448
#define SM_ENV  24576
#define SM_IDX  24608
#define SM_TOT  24672
#define SMEM_BYTES (SM_TOT * 4)
#define UA    0
#define UDOT  32
#define US    48
#define UVY0  80
#define UCRS  128
#define UY1   176
#define USTR  184

__global__ void __launch_bounds__(256, 2) k_edge(
    const float* __restrict__ nf, const int* __restrict__ ei,
    const float* __restrict__ sh, const float* __restrict__ radial,
    const float* __restrict__ env,
    const float* __restrict__ W1, const float* __restrict__ b1,
    const float* __restrict__ b2,
    const float* __restrict__ Wq, const float* __restrict__ bq,
    const float* __restrict__ Wk, const float* __restrict__ bk)
{
    extern __shared__ float sm[];
    const int tid = threadIdx.x;
    const int e0  = blockIdx.x * 32;
    int* isrc = (int*)&sm[SM_IDX];
    int* idst = isrc + 32;
    __nv_bfloat16* hAhi = (__nv_bfloat16*)(sm + SM_AH);
    __nv_bfloat16* hAlo = (__nv_bfloat16*)(sm + SM_AL);
    __nv_bfloat16* wBhi = (__nv_bfloat16*)(sm + SM_BH);
    __nv_bfloat16* wBlo = (__nv_bfloat16*)(sm + SM_BL);

    if (tid < 32) {
        isrc[tid] = ei[e0 + tid];
        idst[tid] = ei[Ee + e0 + tid];
        sm[SM_ENV + tid] = env[e0 + tid];
    }
    if (tid < 128) sm[SM_SH + tid] = sh[e0 * 4 + tid];
    // stage radial into SM_BH scratch [e][17]
    for (int idx = tid; idx < 512; idx += 256) {
        int e = idx >> 4, j = idx & 15;
        sm[SM_BH + e * 17 + j] = radial[(e0 + e) * 16 + j];
    }
    __syncthreads();

    // gather source node features: s_src -> U, v_src -> TP scratch
    for (int idx = tid; idx < 32 * 80; idx += 256) {
        int e = idx / 80, f = idx - e * 80;
        float v = __ldg(&nf[isrc[e] * 80 + f]);
        if (f < 32) sm[SM_U + e * USTR + US + f] = v;
        else        sm[SM_TP + e * 48 + (f - 32)] = v;
    }
    __syncthreads();

    // h = silu(radial @ W1 + b1), split to bf16 hi/lo, layout [e][72]
    {
        int e = tid & 31, r0 = tid >> 5;
        float rr[16];
        #pragma unroll
        for (int j = 0; j < 16; j++) rr[j] = sm[SM_BH + e * 17 + j];
        #pragma unroll
        for (int u = 0; u < 8; u++) {
            int r = r0 + u * 8;
            float x = __ldg(&b1[r]);
            #pragma unroll
            for (int j = 0; j < 16; j++) x += rr[j] * __ldg(&W1[j * 64 + r]);
            x = x / (1.f + expf(-x));
            __nv_bfloat16 hi = __float2bfloat16(x);
            hAhi[e * 72 + r] = hi;
            hAlo[e * 72 + r] = __float2bfloat16(x - __bfloat162float(hi));
        }
    }
    for (int idx = tid; idx < 32 * 84; idx += 256) sm[SM_ACC + idx] = 0.f;
    __syncthreads();   // radial scratch fully consumed; B buffer now free

    // kick off async load of W2 chunk 0 (overlaps u-vector phase)
    #pragma unroll
    for (int j = 0; j < 8; j++) {
        int idx = tid + j * 256;
        int arr = idx >> 10, rem = idx & 1023, n = rem >> 3, seg = (rem & 7) << 3;
        const __nv_bfloat16* s = (arr ? g_w2lo : g_w2hi) + n * 64 + seg;
        __nv_bfloat16* d = (arr ? wBlo : wBhi) + n * 72 + seg;
        cpasync16((unsigned)__cvta_generic_to_shared(d), s);
    }
    asm volatile("cp.async.commit_group;\n");

    // per-edge u vectors
    if (tid < 32) {
        int e = tid;
        float y0  = sm[SM_SH + e * 4 + 0];
        float y1x = sm[SM_SH + e * 4 + 1];
        float y1y = sm[SM_SH + e * 4 + 2];
        float y1z = sm[SM_SH + e * 4 + 3];
        float* U = &sm[SM_U + e * USTR];
        #pragma unroll
        for (int s = 0; s < 32; s++) U[UA + s] = U[US + s] * y0;
        const float is3 = 0.57735026918962576f, is2 = 0.70710678118654752f;
        #pragma unroll
        for (int v = 0; v < 16; v++) {
            float a = sm[SM_TP + e * 48 + v * 3 + 0];
            float b = sm[SM_TP + e * 48 + v * 3 + 1];
            float c = sm[SM_TP + e * 48 + v * 3 + 2];
            U[UDOT + v] = (a * y1x + b * y1y + c * y1z) * is3;
            U[UVY0 + v * 3 + 0] = a * y0;
            U[UVY0 + v * 3 + 1] = b * y0;
            U[UVY0 + v * 3 + 2] = c * y0;
            U[UCRS + v * 3 + 0] = (b * y1z - c * y1y) * is2;
            U[UCRS + v * 3 + 1] = (c * y1x - a * y1z) * is2;
            U[UCRS + v * 3 + 2] = (a * y1y - b * y1x) * is2;
        }
        U[UY1 + 0] = y1x; U[UY1 + 1] = y1y; U[UY1 + 2] = y1z;
    }

    // tensor-core GEMM (32 edges x 2560 cols, K=64) fused with contraction
    const int lane = tid & 31, w = tid >> 5;
    const int mt = w & 1, ng = w >> 1;       // warp: m-tile (16 edges), 32-col group
    const int g  = lane >> 2, tg = lane & 3;

    // ldmatrix addresses: tile index at = lane>>3, row-in-tile ar = lane&7
    const int at = lane >> 3, ar = lane & 7;
    const unsigned aAh = (unsigned)__cvta_generic_to_shared(
        &hAhi[(mt * 16 + (at & 1) * 8 + ar) * 72 + (at >> 1) * 8]);
    const unsigned aAl = aAh + (SM_AL - SM_AH) * 4;
    const unsigned aB0h = (unsigned)__cvta_generic_to_shared(
        &wBhi[(ng * 32 + (at >> 1) * 8 + ar) * 72 + (at & 1) * 8]);
    const unsigned aB1h = aB0h + 16 * 72 * 2;
    const unsigned aB0l = aB0h + (SM_BL - SM_BH) * 4;
    const unsigned aB1l = aB0l + 16 * 72 * 2;

    for (int ch = 0; ch < 20; ch++) {
        const int c0 = ch * 128;
        asm volatile("cp.async.wait_group 0;\n");
        __syncthreads();   // B chunk ready; previous contraction done with TP

        float acc[4][4];
        #pragma unroll
        for (int nt = 0; nt < 4; nt++)
            #pragma unroll
            for (int i = 0; i < 4; i++) acc[nt][i] = 0.f;

        #pragma unroll
        for (int kt = 0; kt < 4; kt++) {
            const unsigned off = kt * 32;   // 16 halves = 32 bytes
            unsigned ah[4], al[4], b0h[4], b1h[4], b0l[4], b1l[4];
            ldsm4(ah, aAh + off);
            ldsm4(al, aAl + off);
            ldsm4(b0h, aB0h + off);
            ldsm4(b1h, aB1h + off);
            ldsm4(b0l, aB0l + off);
            ldsm4(b1l, aB1l + off);
            mma_bf16(acc[0], ah, b0h + 0); mma_bf16(acc[1], ah, b0h + 2);
            mma_bf16(acc[2], ah, b1h + 0); mma_bf16(acc[3], ah, b1h + 2);
            mma_bf16(acc[0], ah, b0l + 0); mma_bf16(acc[1], ah, b0l + 2);
            mma_bf16(acc[2], ah, b1l + 0); mma_bf16(acc[3], ah, b1l + 2);
            mma_bf16(acc[0], al, b0h + 0); mma_bf16(acc[1], al, b0h + 2);
            mma_bf16(acc[2], al, b1h + 0); mma_bf16(acc[3], al, b1h + 2);
        }

        // store tp tile (+bias)
        #pragma unroll
        for (int nt = 0; nt < 4; nt++) {
            const int col = ng * 32 + nt * 8 + tg * 2;
            const float bx = __ldg(&b2[c0 + col]);
            const float by = __ldg(&b2[c0 + col + 1]);
            const int r0 = mt * 16 + g;
            float2 v0 = { acc[nt][0] + bx, acc[nt][1] + by };
            float2 v1 = { acc[nt][2] + bx, acc[nt][3] + by };
            *(float2*)&sm[SM_TP + r0 * 136 + col] = v0;
            *(float2*)&sm[SM_TP + (r0 + 8) * 136 + col] = v1;
        }
        __syncthreads();   // all B reads done, TP visible

        // issue next W2 chunk load (overlaps contraction)
        if (ch < 19) {
            const int c1 = (ch + 1) * 128;
            #pragma unroll
            for (int j = 0; j < 8; j++) {
                int idx = tid + j * 256;
                int arr = idx >> 10, rem = idx & 1023, n = rem >> 3, seg = (rem & 7) << 3;
                const __nv_bfloat16* s = (arr ? g_w2lo : g_w2hi) + (c1 + n) * 64 + seg;
                __nv_bfloat16* d = (arr ? wBlo : wBhi) + n * 72 + seg;
                cpasync16((unsigned)__cvta_generic_to_shared(d), s);
            }
            asm volatile("cp.async.commit_group;\n");
        }

        // contraction of this chunk into message accumulators
        if (ch < 12) {  // WA (s-major) or WB (v-major), 32 outputs
            int uoff = (ch < 8) ? (UA + ch * 4) : (UDOT + (ch - 8) * 4);
            int k = tid & 31, eb = tid >> 5;
            #pragma unroll
            for (int jj = 0; jj < 4; jj++) {
                int e = eb + jj * 8;
                const float* t = &sm[SM_TP + e * 136];
                const float* U = &sm[SM_U + e * USTR + uoff];
                sm[SM_ACC + e * 84 + k] +=
                    t[k] * U[0] + t[32 + k] * U[1] + t[64 + k] * U[2] + t[96 + k] * U[3];
            }
        } else {        // WC / WD / WE, 16 vector outputs x 3 components
            int k = tid & 15, eb = tid >> 4;
            #pragma unroll
            for (int jj = 0; jj < 2; jj++) {
                int e = eb + jj * 16;
                const float* t = &sm[SM_TP + e * 136];
                const float* U = &sm[SM_U + e * USTR];
                float* A = &sm[SM_ACC + e * 84 + 32 + k * 3];
                if (ch < 16) {
                    int i0 = US + (ch - 12) * 8;
                    float tC = 0.f;
                    #pragma unroll
                    for (int i = 0; i < 8; i++) tC += t[i * 16 + k] * U[i0 + i];
                    A[0] += tC * U[UY1 + 0];
                    A[1] += tC * U[UY1 + 1];
                    A[2] += tC * U[UY1 + 2];
                } else {
                    int ub = (ch < 18) ? (UVY0 + (ch - 16) * 24) : (UCRS + (ch - 18) * 24);
                    float s0 = 0.f, s1 = 0.f, s2 = 0.f;
                    #pragma unroll
                    for (int i = 0; i < 8; i++) {
                        float tv = t[i * 16 + k];
                        s0 += tv * U[ub + i * 3 + 0];
                        s1 += tv * U[ub + i * 3 + 1];
                        s2 += tv * U[ub + i * 3 + 2];
                    }
                    A[0] += s0; A[1] += s1; A[2] += s2;
                }
            }
        }
    }
    __syncthreads();

    // scale + write messages; gather dst scalars for q (SM_BH scratch)
    const float A0c = 0.14433756729740643f;  // 1/sqrt(48)
    const float A1c = 0.125f;                // 1/sqrt(64)
    for (int idx = tid; idx < 2560; idx += 256) {
        int e = idx / 80, f = idx - e * 80;
        float m = sm[SM_ACC + e * 84 + f] * (f < 32 ? A0c : A1c);
        sm[SM_ACC + e * 84 + f] = m;
        g_msg[(e0 + e) * 80 + f] = m;
    }
    for (int idx = tid; idx < 1024; idx += 256) {
        int e = idx >> 5, f = idx & 31;
        sm[SM_BH + e * 33 + f] = __ldg(&nf[idst[e] * 80 + f]);
    }
    __syncthreads();
    {
        int e = tid >> 3, j = tid & 7;
        float kh = __ldg(&bk[j]), qh = __ldg(&bq[j]);
        #pragma unroll
        for (int k = 0; k < 32; k++) {
            kh += sm[SM_ACC + e * 84 + k] * __ldg(&Wk[k * 8 + j]);
            qh += sm[SM_BH + e * 33 + k] * __ldg(&Wq[k * 8 + j]);
        }
        float p = kh * qh;
        p += __shfl_down_sync(0xffffffffu, p, 4, 8);
        p += __shfl_down_sync(0xffffffffu, p, 2, 8);
        p += __shfl_down_sync(0xffffffffu, p, 1, 8);
        if (j == 0) {
            float lg = p * 0.35355339059327373f + logf(sm[SM_ENV + e] + 1e-8f);
            g_logit[e0 + e] = lg;
            atomicMax(&g_max[idst[e]], fenc(lg));
        }
    }
}

__global__ void k_soft(const int* __restrict__ ei) {
    int e = blockIdx.x * blockDim.x + threadIdx.x;
    if (e >= Ee) return;
    int dst = ei[Ee + e];
    float ex = expf(g_logit[e] - fdec(g_max[dst]));
    g_ex[e] = ex;
    atomicAdd(&g_den[dst], ex);
}

__global__ void k_agg(const int* __restrict__ ei) {
    int idx = blockIdx.x * blockDim.x + threadIdx.x;
    if (idx >= Ee * 80) return;
    unsigned e = (unsigned)idx / 80u;
    int f = idx - (int)e * 80;
    int dst = ei[Ee + e];
    float attn = g_ex[e] / (g_den[dst] + 1e-8f);
    atomicAdd(&g_agg[dst * 80 + f], attn * g_msg[idx]);
}

__global__ void __launch_bounds__(256) k_node(
    const float* __restrict__ nf,
    const float* __restrict__ Wout_s, const float* __restrict__ Wout_v,
    const float* __restrict__ Wg_s,   const float* __restrict__ Wg_v)
{
    __shared__ float ws[1024], wgs[1536], wv[256], wgv[256], st[80];
    int tid = threadIdx.x;
    for (int i = tid; i < 1024; i += 256) ws[i] = Wout_s[i];
    for (int i = tid; i < 1536; i += 256) wgs[i] = Wg_s[i];
    wv[tid]  = Wout_v[tid];
    wgv[tid] = Wg_v[tid];
    if (tid < 80) st[tid] = 0.f;
    __syncthreads();

    int n = blockIdx.x * 256 + tid;
    bool act = (n < Nn);
    const float isS = 0.17677669529663687f;
    int lane = tid & 31;

    float xs[32], gsig[16];
    if (act) {
        float as[32], a2[32], gsv[48];
        #pragma unroll
        for (int s = 0; s < 32; s++) as[s] = g_agg[n * 80 + s];
        #pragma unroll
        for (int k = 0; k < 32; k++) {
            float a = 0.f;
            #pragma unroll
            for (int s = 0; s < 32; s++) a += as[s] * ws[s * 32 + k];
            a2[k] = a * isS;
        }
        #pragma unroll
        for (int j = 0; j < 48; j++) {
            float a = 0.f;
            #pragma unroll
            for (int s = 0; s < 32; s++) a += a2[s] * wgs[s * 48 + j];
            gsv[j] = a * isS;
        }
        #pragma unroll
        for (int k = 0; k < 32; k++) {
            float v = gsv[k];
            xs[k] = v / (1.f + expf(-v)) + nf[n * 80 + k];
        }
        #pragma unroll
        for (int k = 0; k < 16; k++) gsig[k] = 1.f / (1.f + expf(-gsv[32 + k]));
    } else {
        #pragma unroll
        for (int k = 0; k < 32; k++) xs[k] = 0.f;
        #pragma unroll
        for (int k = 0; k < 16; k++) gsig[k] = 0.f;
    }
    #pragma unroll
    for (int k = 0; k < 32; k++) {
        if (act) g_x[n * 80 + k] = xs[k];
        float s1 = warpsum(xs[k]);
        float s2 = warpsum(xs[k] * xs[k]);
        if (lane == 0) { atomicAdd(&st[k], s1); atomicAdd(&st[32 + k], s2); }
    }

    float vsum[16];
    #pragma unroll
    for (int w = 0; w < 16; w++) vsum[w] = 0.f;
    for (int c = 0; c < 3; c++) {
        float xv[16];
        if (act) {
            float av[16], a2v[16];
            #pragma unroll
            for (int v = 0; v < 16; v++) av[v] = g_agg[n * 80 + 32 + v * 3 + c];
            #pragma unroll
            for (int w = 0; w < 16; w++) {
                float a = 0.f;
                #pragma unroll
                for (int v = 0; v < 16; v++) a += av[v] * wv[v * 16 + w];
                a2v[w] = a * 0.25f;
            }
            #pragma unroll
            for (int w = 0; w < 16; w++) {
                float a = 0.f;
                #pragma unroll
                for (int v = 0; v < 16; v++) a += a2v[v] * wgv[v * 16 + w];
                float x = gsig[w] * (a * 0.25f) + nf[n * 80 + 32 + w * 3 + c];
                xv[w] = x;
                g_x[n * 80 + 32 + w * 3 + c] = x;
            }
        } else {
            #pragma unroll
            for (int w = 0; w < 16; w++) xv[w] = 0.f;
        }
        #pragma unroll
        for (int w = 0; w < 16; w++) vsum[w] += xv[w] * xv[w];
    }
    #pragma unroll
    for (int w = 0; w < 16; w++) {
        float s = warpsum(vsum[w]);
        if (lane == 0) atomicAdd(&st[64 + w], s);
    }
    __syncthreads();
    if (tid < 80) atomicAdd(&g_stats[tid], st[tid]);
}

__global__ void k_stats(const float* __restrict__ bn_ws,
                        const float* __restrict__ bn_bs,
                        const float* __restrict__ bn_wv) {
    int i = threadIdx.x;
    if (i < 32) {
        float mean = g_stats[i] / (float)Nn;
        float var  = g_stats[32 + i] / (float)Nn - mean * mean;
        float sc   = bn_ws[i] / sqrtf(var + 1e-5f);
        g_norm[i]      = sc;
        g_norm[32 + i] = bn_bs[i] - mean * sc;
    } else if (i < 48) {
        int v = i - 32;
        float vn = g_stats[64 + v] / (3.f * (float)Nn);
        g_norm[64 + v] = bn_wv[v] / sqrtf(vn + 1e-5f);
    }
}

__global__ void k_out(float* __restrict__ out) {
    int idx = blockIdx.x * blockDim.x + threadIdx.x;
    if (idx >= Nn * 80) return;
    int f = idx % 80;
    float x = g_x[idx];
    if (f < 32) out[idx] = x * g_norm[f] + g_norm[32 + f];
    else        out[idx] = x * g_norm[64 + (f - 32) / 3];
}

extern "C" void kernel_launch(void* const* d_in, const int* in_sizes, int n_in,
                              void* d_out, int out_size) {
    const float* nf     = (const float*)d_in[0];
    const int*   ei     = (const int*)  d_in[1];
    const float* sh     = (const float*)d_in[2];
    const float* radial = (const float*)d_in[3];
    const float* env    = (const float*)d_in[4];
    const float* W1     = (const float*)d_in[5];
    const float* b1     = (const float*)d_in[6];
    const float* W2     = (const float*)d_in[7];
    const float* b2     = (const float*)d_in[8];
    const float* Wq     = (const float*)d_in[9];
    const float* bq     = (const float*)d_in[10];
    const float* Wk     = (const float*)d_in[11];
    const float* bk     = (const float*)d_in[12];
    const float* Wout_s = (const float*)d_in[13];
    const float* Wout_v = (const float*)d_in[14];
    const float* Wg_s   = (const float*)d_in[15];
    const float* Wg_v   = (const float*)d_in[16];
    const float* bn_ws  = (const float*)d_in[17];
    const float* bn_bs  = (const float*)d_in[18];
    const float* bn_wv  = (const float*)d_in[19];
    float* out = (float*)d_out;

    cudaFuncSetAttribute(k_edge, cudaFuncAttributeMaxDynamicSharedMemorySize, SMEM_BYTES);

    k_init<<<1024, 256>>>();
    k_prep<<<40, 256>>>(W2);
    k_edge<<<Ee / 32, 256, SMEM_BYTES>>>(nf, ei, sh, radial, env,
                                         W1, b1, b2, Wq, bq, Wk, bk);
    k_soft<<<(Ee + 255) / 256, 256>>>(ei);
    k_agg<<<(Ee * 80 + 255) / 256, 256>>>(ei);
    k_node<<<(Nn + 255) / 256, 256>>>(nf, Wout_s, Wout_v, Wg_s, Wg_v);
    k_stats<<<1, 64>>>(bn_ws, bn_bs, bn_wv);
    k_out<<<(Nn * 80 + 255) / 256, 256>>>(out);
}

// round 17
// speedup vs baseline: 1.6353x; 1.0184x over previous
#include <cuda_runtime.h>
#include <cuda_bf16.h>
#include <math.h>

#define Nn   10000
#define Ee   100000

__device__ float    g_msg[Ee * 80];
__device__ float    g_logit[Ee];
__device__ float    g_ex[Ee];
__device__ unsigned g_max[Nn];
__device__ float    g_den[Nn];
__device__ float    g_agg[Nn * 80];
__device__ float    g_x[Nn * 80];
__device__ float    g_stats[80];
__device__ float    g_norm[80];
// W2 pre-split into bf16 hi/lo, TRANSPOSED to [col][k] (col=0..2559, k=0..63)
__device__ __nv_bfloat16 g_w2hi[2560 * 64];
__device__ __nv_bfloat16 g_w2lo[2560 * 64];

__device__ __forceinline__ unsigned fenc(float f) {
    unsigned b = __float_as_uint(f);
    return (b & 0x80000000u) ? ~b : (b | 0x80000000u);
}
__device__ __forceinline__ float fdec(unsigned u) {
    return (u & 0x80000000u) ? __uint_as_float(u & 0x7fffffffu) : __uint_as_float(~u);
}
__device__ __forceinline__ float warpsum(float v) {
    #pragma unroll
    for (int o = 16; o; o >>= 1) v += __shfl_xor_sync(0xffffffffu, v, o);
    return v;
}
__device__ __forceinline__ void mma_bf16(float* d, const unsigned* a, const unsigned* b) {
    asm volatile(
        "mma.sync.aligned.m16n8k16.row.col.f32.bf16.bf16.f32 "
        "{%0,%1,%2,%3}, {%4,%5,%6,%7}, {%8,%9}, {%0,%1,%2,%3};\n"
        : "+f"(d[0]), "+f"(d[1]), "+f"(d[2]), "+f"(d[3])
        : "r"(a[0]), "r"(a[1]), "r"(a[2]), "r"(a[3]), "r"(b[0]), "r"(b[1]));
}
__device__ __forceinline__ void ldsm4(unsigned* r, unsigned addr) {
    asm volatile("ldmatrix.sync.aligned.m8n8.x4.shared.b16 {%0,%1,%2,%3}, [%4];\n"
        : "=r"(r[0]), "=r"(r[1]), "=r"(r[2]), "=r"(r[3]) : "r"(addr));
}
__device__ __forceinline__ void cpasync16(unsigned s, const void* g) {
    asm volatile("cp.async.cg.shared.global [%0], [%1], 16;\n" :: "r"(s), "l"(g));
}

__global__ void k_init() {
    int i = blockIdx.x * blockDim.x + threadIdx.x;
    int st = gridDim.x * blockDim.x;
    for (int x = i; x < Nn * 80; x += st) g_agg[x] = 0.f;
    for (int x = i; x < Nn; x += st) { g_den[x] = 0.f; g_max[x] = 0u; }
    if (i < 80) g_stats[i] = 0.f;
}

// split + transpose W2 (coalesced both sides via smem tile)
__global__ void __launch_bounds__(256) k_prep(const float* __restrict__ W2) {
    __shared__ float tile[64][65];
    int c0 = blockIdx.x * 64;
    int tid = threadIdx.x;
    for (int i = tid; i < 4096; i += 256) {
        int r = i >> 6, c = i & 63;
        tile[r][c] = W2[r * 2560 + c0 + c];
    }
    __syncthreads();
    for (int i = tid; i < 4096; i += 256) {
        int c = i >> 6, r = i & 63;
        float x = tile[r][c];
        __nv_bfloat16 hi = __float2bfloat16(x);
        g_w2hi[(c0 + c) * 64 + r] = hi;
        g_w2lo[(c0 + c) * 64 + r] = __float2bfloat16(x - __bfloat162float(hi));
    }
}

// ------------- smem layout (float offsets) -------------
#define SM_AH   0        // h hi bf16 [32 rows][72 halves] = 1152 floats
#define SM_AL   1152     // h lo
#define SM_BH   2304     // W2 chunk hi bf16 [128 cols][72 halves] = 4608 floats
#define SM_BL   6912     // W2 chunk lo
#define SM_TP   11520    // tp tile fp32 [32][136] ; also partial buf [4][32][34]
#define SM_U    15872    // per-edge u vectors [32][184]
#define SM_ACC  21760    // msg accumulators [32][84]
#define SM_SH   24448
#define SM_ENV  24576
#define SM_IDX  24608
#define SM_TOT  24672
#define SMEM_BYTES (SM_TOT * 4)
#define UA    0
#define UDOT  32
#define US    48
#define UVY0  80
#define UCRS  128
#define UY1   176
#define USTR  184

__global__ void __launch_bounds__(256, 2) k_edge(
    const float* __restrict__ nf, const int* __restrict__ ei,
    const float* __restrict__ sh, const float* __restrict__ radial,
    const float* __restrict__ env,
    const float* __restrict__ W1, const float* __restrict__ b1,
    const float* __restrict__ b2,
    const float* __restrict__ Wq, const float* __restrict__ bq,
    const float* __restrict__ Wk, const float* __restrict__ bk)
{
    extern __shared__ float sm[];
    const int tid = threadIdx.x;
    const int e0  = blockIdx.x * 32;
    int* isrc = (int*)&sm[SM_IDX];
    int* idst = isrc + 32;
    __nv_bfloat16* hAhi = (__nv_bfloat16*)(sm + SM_AH);
    __nv_bfloat16* hAlo = (__nv_bfloat16*)(sm + SM_AL);
    __nv_bfloat16* wBhi = (__nv_bfloat16*)(sm + SM_BH);
    __nv_bfloat16* wBlo = (__nv_bfloat16*)(sm + SM_BL);

    if (tid < 32) {
        isrc[tid] = ei[e0 + tid];
        idst[tid] = ei[Ee + e0 + tid];
        sm[SM_ENV + tid] = env[e0 + tid];
    }
    if (tid < 128) sm[SM_SH + tid] = sh[e0 * 4 + tid];
    // stage radial into SM_BH scratch [e][17]
    for (int idx = tid; idx < 512; idx += 256) {
        int e = idx >> 4, j = idx & 15;
        sm[SM_BH + e * 17 + j] = radial[(e0 + e) * 16 + j];
    }
    __syncthreads();

    // gather source node features: s_src -> U, v_src -> TP scratch
    for (int idx = tid; idx < 32 * 80; idx += 256) {
        int e = idx / 80, f = idx - e * 80;
        float v = __ldg(&nf[isrc[e] * 80 + f]);
        if (f < 32) sm[SM_U + e * USTR + US + f] = v;
        else        sm[SM_TP + e * 48 + (f - 32)] = v;
    }
    __syncthreads();

    // h = silu(radial @ W1 + b1), split to bf16 hi/lo, layout [e][72]
    {
        int e = tid & 31, r0 = tid >> 5;
        float rr[16];
        #pragma unroll
        for (int j = 0; j < 16; j++) rr[j] = sm[SM_BH + e * 17 + j];
        #pragma unroll
        for (int u = 0; u < 8; u++) {
            int r = r0 + u * 8;
            float x = __ldg(&b1[r]);
            #pragma unroll
            for (int j = 0; j < 16; j++) x += rr[j] * __ldg(&W1[j * 64 + r]);
            x = x / (1.f + expf(-x));
            __nv_bfloat16 hi = __float2bfloat16(x);
            hAhi[e * 72 + r] = hi;
            hAlo[e * 72 + r] = __float2bfloat16(x - __bfloat162float(hi));
        }
    }
    for (int idx = tid; idx < 32 * 84; idx += 256) sm[SM_ACC + idx] = 0.f;
    __syncthreads();   // radial scratch fully consumed; B buffer now free

    // kick off async load of W2 chunk 0 (overlaps u-vector phase)
    #pragma unroll
    for (int j = 0; j < 8; j++) {
        int idx = tid + j * 256;
        int arr = idx >> 10, rem = idx & 1023, n = rem >> 3, seg = (rem & 7) << 3;
        const __nv_bfloat16* s = (arr ? g_w2lo : g_w2hi) + n * 64 + seg;
        __nv_bfloat16* d = (arr ? wBlo : wBhi) + n * 72 + seg;
        cpasync16((unsigned)__cvta_generic_to_shared(d), s);
    }
    asm volatile("cp.async.commit_group;\n");

    // per-edge u vectors
    if (tid < 32) {
        int e = tid;
        float y0  = sm[SM_SH + e * 4 + 0];
        float y1x = sm[SM_SH + e * 4 + 1];
        float y1y = sm[SM_SH + e * 4 + 2];
        float y1z = sm[SM_SH + e * 4 + 3];
        float* U = &sm[SM_U + e * USTR];
        #pragma unroll
        for (int s = 0; s < 32; s++) U[UA + s] = U[US + s] * y0;
        const float is3 = 0.57735026918962576f, is2 = 0.70710678118654752f;
        #pragma unroll
        for (int v = 0; v < 16; v++) {
            float a = sm[SM_TP + e * 48 + v * 3 + 0];
            float b = sm[SM_TP + e * 48 + v * 3 + 1];
            float c = sm[SM_TP + e * 48 + v * 3 + 2];
            U[UDOT + v] = (a * y1x + b * y1y + c * y1z) * is3;
            U[UVY0 + v * 3 + 0] = a * y0;
            U[UVY0 + v * 3 + 1] = b * y0;
            U[UVY0 + v * 3 + 2] = c * y0;
            U[UCRS + v * 3 + 0] = (b * y1z - c * y1y) * is2;
            U[UCRS + v * 3 + 1] = (c * y1x - a * y1z) * is2;
            U[UCRS + v * 3 + 2] = (a * y1y - b * y1x) * is2;
        }
        U[UY1 + 0] = y1x; U[UY1 + 1] = y1y; U[UY1 + 2] = y1z;
    }

    // tensor-core GEMM (32 edges x 2560 cols, K=64) fused with contraction
    const int lane = tid & 31, w = tid >> 5;
    const int mt = w & 1, ng = w >> 1;       // warp: m-tile (16 edges), 32-col group
    const int g  = lane >> 2, tg = lane & 3;

    // ldmatrix addresses: tile index at = lane>>3, row-in-tile ar = lane&7
    const int at = lane >> 3, ar = lane & 7;
    const unsigned aAh = (unsigned)__cvta_generic_to_shared(
        &hAhi[(mt * 16 + (at & 1) * 8 + ar) * 72 + (at >> 1) * 8]);
    const unsigned aAl = aAh + (SM_AL - SM_AH) * 4;
    const unsigned aB0h = (unsigned)__cvta_generic_to_shared(
        &wBhi[(ng * 32 + (at >> 1) * 8 + ar) * 72 + (at & 1) * 8]);
    const unsigned aB1h = aB0h + 16 * 72 * 2;
    const unsigned aB0l = aB0h + (SM_BL - SM_BH) * 4;
    const unsigned aB1l = aB0l + 16 * 72 * 2;

    // persistent register accumulator for WA/WB fragment-direct contraction
    float macc[4][4];
    #pragma unroll
    for (int nt = 0; nt < 4; nt++)
        #pragma unroll
        for (int i = 0; i < 4; i++) macc[nt][i] = 0.f;

    for (int ch = 0; ch < 20; ch++) {
        const int c0 = ch * 128;
        asm volatile("cp.async.wait_group 0;\n");
        __syncthreads();   // B chunk ready; previous phase done

        float acc[4][4];
        #pragma unroll
        for (int nt = 0; nt < 4; nt++)
            #pragma unroll
            for (int i = 0; i < 4; i++) acc[nt][i] = 0.f;

        #pragma unroll
        for (int kt = 0; kt < 4; kt++) {
            const unsigned off = kt * 32;   // 16 halves = 32 bytes
            unsigned ah[4], al[4], b0h[4], b1h[4], b0l[4], b1l[4];
            ldsm4(ah, aAh + off);
            ldsm4(al, aAl + off);
            ldsm4(b0h, aB0h + off);
            ldsm4(b1h, aB1h + off);
            ldsm4(b0l, aB0l + off);
            ldsm4(b1l, aB1l + off);
            mma_bf16(acc[0], ah, b0h + 0); mma_bf16(acc[1], ah, b0h + 2);
            mma_bf16(acc[2], ah, b1h + 0); mma_bf16(acc[3], ah, b1h + 2);
            mma_bf16(acc[0], ah, b0l + 0); mma_bf16(acc[1], ah, b0l + 2);
            mma_bf16(acc[2], ah, b1l + 0); mma_bf16(acc[3], ah, b1l + 2);
            mma_bf16(acc[0], al, b0h + 0); mma_bf16(acc[1], al, b0h + 2);
            mma_bf16(acc[2], al, b1h + 0); mma_bf16(acc[3], al, b1h + 2);
        }

        if (ch < 12) {
            // fragment-direct contraction: warp ng owns s = ch*4+ng (WA) or
            // v = (ch-8)*4+ng (WB); lane rows e_a = mt*16+g, e_b = e_a+8.
            const int uoff = (ch < 8 ? UA + ch * 4 : UDOT + (ch - 8) * 4) + ng;
            const float ua = sm[SM_U + (mt * 16 + g) * USTR + uoff];
            const float ub = sm[SM_U + (mt * 16 + g + 8) * USTR + uoff];
            #pragma unroll
            for (int nt = 0; nt < 4; nt++) {
                const int col = ng * 32 + nt * 8 + tg * 2;
                const float bx = __ldg(&b2[c0 + col]);
                const float by = __ldg(&b2[c0 + col + 1]);
                macc[nt][0] += ua * (acc[nt][0] + bx);
                macc[nt][1] += ua * (acc[nt][1] + by);
                macc[nt][2] += ub * (acc[nt][2] + bx);
                macc[nt][3] += ub * (acc[nt][3] + by);
            }
            if (ch == 11) {
                // dump per-ng partials into TP region: P[ng][e][k], stride 34
                #pragma unroll
                for (int nt = 0; nt < 4; nt++) {
                    const int k = nt * 8 + tg * 2;
                    float2 p0 = { macc[nt][0], macc[nt][1] };
                    float2 p1 = { macc[nt][2], macc[nt][3] };
                    *(float2*)&sm[SM_TP + ng * 1088 + (mt * 16 + g) * 34 + k] = p0;
                    *(float2*)&sm[SM_TP + ng * 1088 + (mt * 16 + g + 8) * 34 + k] = p1;
                }
            }
            __syncthreads();   // B reads + (ch==11) partial dump complete
            // issue next W2 chunk load
            {
                const int c1 = (ch + 1) * 128;
                #pragma unroll
                for (int j = 0; j < 8; j++) {
                    int idx = tid + j * 256;
                    int arr = idx >> 10, rem = idx & 1023, n = rem >> 3, seg = (rem & 7) << 3;
                    const __nv_bfloat16* s = (arr ? g_w2lo : g_w2hi) + (c1 + n) * 64 + seg;
                    __nv_bfloat16* d = (arr ? wBlo : wBhi) + n * 72 + seg;
                    cpasync16((unsigned)__cvta_generic_to_shared(d), s);
                }
                asm volatile("cp.async.commit_group;\n");
            }
            if (ch == 11) {
                // reduce the 4 ng-partials into ACC msg_s slots
                #pragma unroll
                for (int q = 0; q < 4; q++) {
                    int o = tid * 4 + q;          // 0..1023
                    int e = o >> 5, k = o & 31;
                    float v = sm[SM_TP + e * 34 + k]
                            + sm[SM_TP + 1088 + e * 34 + k]
                            + sm[SM_TP + 2176 + e * 34 + k]
                            + sm[SM_TP + 3264 + e * 34 + k];
                    sm[SM_ACC + e * 84 + k] = v;
                }
            }
        } else {
            // store tp tile (+bias)
            #pragma unroll
            for (int nt = 0; nt < 4; nt++) {
                const int col = ng * 32 + nt * 8 + tg * 2;
                const float bx = __ldg(&b2[c0 + col]);
                const float by = __ldg(&b2[c0 + col + 1]);
                const int r0 = mt * 16 + g;
                float2 v0 = { acc[nt][0] + bx, acc[nt][1] + by };
                float2 v1 = { acc[nt][2] + bx, acc[nt][3] + by };
                *(float2*)&sm[SM_TP + r0 * 136 + col] = v0;
                *(float2*)&sm[SM_TP + (r0 + 8) * 136 + col] = v1;
            }
            __syncthreads();   // all B reads done, TP visible

            // issue next W2 chunk load (overlaps contraction)
            if (ch < 19) {
                const int c1 = (ch + 1) * 128;
                #pragma unroll
                for (int j = 0; j < 8; j++) {
                    int idx = tid + j * 256;
                    int arr = idx >> 10, rem = idx & 1023, n = rem >> 3, seg = (rem & 7) << 3;
                    const __nv_bfloat16* s = (arr ? g_w2lo : g_w2hi) + (c1 + n) * 64 + seg;
                    __nv_bfloat16* d = (arr ? wBlo : wBhi) + n * 72 + seg;
                    cpasync16((unsigned)__cvta_generic_to_shared(d), s);
                }
                asm volatile("cp.async.commit_group;\n");
            }

            // contraction: WC / WD / WE, 16 vector outputs x 3 components
            int k = tid & 15, eb = tid >> 4;
            #pragma unroll
            for (int jj = 0; jj < 2; jj++) {
                int e = eb + jj * 16;
                const float* t = &sm[SM_TP + e * 136];
                const float* U = &sm[SM_U + e * USTR];
                float* A = &sm[SM_ACC + e * 84 + 32 + k * 3];
                if (ch < 16) {
                    int i0 = US + (ch - 12) * 8;
                    float tC = 0.f;
                    #pragma unroll
                    for (int i = 0; i < 8; i++) tC += t[i * 16 + k] * U[i0 + i];
                    A[0] += tC * U[UY1 + 0];
                    A[1] += tC * U[UY1 + 1];
                    A[2] += tC * U[UY1 + 2];
                } else {
                    int ub = (ch < 18) ? (UVY0 + (ch - 16) * 24) : (UCRS + (ch - 18) * 24);
                    float s0 = 0.f, s1 = 0.f, s2 = 0.f;
                    #pragma unroll
                    for (int i = 0; i < 8; i++) {
                        float tv = t[i * 16 + k];
                        s0 += tv * U[ub + i * 3 + 0];
                        s1 += tv * U[ub + i * 3 + 1];
                        s2 += tv * U[ub + i * 3 + 2];
                    }
                    A[0] += s0; A[1] += s1; A[2] += s2;
                }
            }
        }
    }
    __syncthreads();

    // scale + write messages; gather dst scalars for q (SM_BH scratch)
    const float A0c = 0.14433756729740643f;  // 1/sqrt(48)
    const float A1c = 0.125f;                // 1/sqrt(64)
    for (int idx = tid; idx < 2560; idx += 256) {
        int e = idx / 80, f = idx - e * 80;
        float m = sm[SM_ACC + e * 84 + f] * (f < 32 ? A0c : A1c);
        sm[SM_ACC + e * 84 + f] = m;
        g_msg[(e0 + e) * 80 + f] = m;
    }
    for (int idx = tid; idx < 1024; idx += 256) {
        int e = idx >> 5, f = idx & 31;
        sm[SM_BH + e * 33 + f] = __ldg(&nf[idst[e] * 80 + f]);
    }
    __syncthreads();
    {
        int e = tid >> 3, j = tid & 7;
        float kh = __ldg(&bk[j]), qh = __ldg(&bq[j]);
        #pragma unroll
        for (int k = 0; k < 32; k++) {
            kh += sm[SM_ACC + e * 84 + k] * __ldg(&Wk[k * 8 + j]);
            qh += sm[SM_BH + e * 33 + k] * __ldg(&Wq[k * 8 + j]);
        }
        float p = kh * qh;
        p += __shfl_down_sync(0xffffffffu, p, 4, 8);
        p += __shfl_down_sync(0xffffffffu, p, 2, 8);
        p += __shfl_down_sync(0xffffffffu, p, 1, 8);
        if (j == 0) {
            float lg = p * 0.35355339059327373f + logf(sm[SM_ENV + e] + 1e-8f);
            g_logit[e0 + e] = lg;
            atomicMax(&g_max[idst[e]], fenc(lg));
        }
    }
}

__global__ void k_soft(const int* __restrict__ ei) {
    int e = blockIdx.x * blockDim.x + threadIdx.x;
    if (e >= Ee) return;
    int dst = ei[Ee + e];
    float ex = expf(g_logit[e] - fdec(g_max[dst]));
    g_ex[e] = ex;
    atomicAdd(&g_den[dst], ex);
}

__global__ void k_agg(const int* __restrict__ ei) {
    int idx = blockIdx.x * blockDim.x + threadIdx.x;
    if (idx >= Ee * 80) return;
    unsigned e = (unsigned)idx / 80u;
    int f = idx - (int)e * 80;
    int dst = ei[Ee + e];
    float attn = g_ex[e] / (g_den[dst] + 1e-8f);
    atomicAdd(&g_agg[dst * 80 + f], attn * g_msg[idx]);
}

__global__ void __launch_bounds__(256) k_node(
    const float* __restrict__ nf,
    const float* __restrict__ Wout_s, const float* __restrict__ Wout_v,
    const float* __restrict__ Wg_s,   const float* __restrict__ Wg_v)
{
    __shared__ float ws[1024], wgs[1536], wv[256], wgv[256], st[80];
    int tid = threadIdx.x;
    for (int i = tid; i < 1024; i += 256) ws[i] = Wout_s[i];
    for (int i = tid; i < 1536; i += 256) wgs[i] = Wg_s[i];
    wv[tid]  = Wout_v[tid];
    wgv[tid] = Wg_v[tid];
    if (tid < 80) st[tid] = 0.f;
    __syncthreads();

    int n = blockIdx.x * 256 + tid;
    bool act = (n < Nn);
    const float isS = 0.17677669529663687f;
    int lane = tid & 31;

    float xs[32], gsig[16];
    if (act) {
        float as[32], a2[32], gsv[48];
        #pragma unroll
        for (int s = 0; s < 32; s++) as[s] = g_agg[n * 80 + s];
        #pragma unroll
        for (int k = 0; k < 32; k++) {
            float a = 0.f;
            #pragma unroll
            for (int s = 0; s < 32; s++) a += as[s] * ws[s * 32 + k];
            a2[k] = a * isS;
        }
        #pragma unroll
        for (int j = 0; j < 48; j++) {
            float a = 0.f;
            #pragma unroll
            for (int s = 0; s < 32; s++) a += a2[s] * wgs[s * 48 + j];
            gsv[j] = a * isS;
        }
        #pragma unroll
        for (int k = 0; k < 32; k++) {
            float v = gsv[k];
            xs[k] = v / (1.f + expf(-v)) + nf[n * 80 + k];
        }
        #pragma unroll
        for (int k = 0; k < 16; k++) gsig[k] = 1.f / (1.f + expf(-gsv[32 + k]));
    } else {
        #pragma unroll
        for (int k = 0; k < 32; k++) xs[k] = 0.f;
        #pragma unroll
        for (int k = 0; k < 16; k++) gsig[k] = 0.f;
    }
    #pragma unroll
    for (int k = 0; k < 32; k++) {
        if (act) g_x[n * 80 + k] = xs[k];
        float s1 = warpsum(xs[k]);
        float s2 = warpsum(xs[k] * xs[k]);
        if (lane == 0) { atomicAdd(&st[k], s1); atomicAdd(&st[32 + k], s2); }
    }

    float vsum[16];
    #pragma unroll
    for (int w = 0; w < 16; w++) vsum[w] = 0.f;
    for (int c = 0; c < 3; c++) {
        float xv[16];
        if (act) {
            float av[16], a2v[16];
            #pragma unroll
            for (int v = 0; v < 16; v++) av[v] = g_agg[n * 80 + 32 + v * 3 + c];
            #pragma unroll
            for (int w = 0; w < 16; w++) {
                float a = 0.f;
                #pragma unroll
                for (int v = 0; v < 16; v++) a += av[v] * wv[v * 16 + w];
                a2v[w] = a * 0.25f;
            }
            #pragma unroll
            for (int w = 0; w < 16; w++) {
                float a = 0.f;
                #pragma unroll
                for (int v = 0; v < 16; v++) a += a2v[v] * wgv[v * 16 + w];
                float x = gsig[w] * (a * 0.25f) + nf[n * 80 + 32 + w * 3 + c];
                xv[w] = x;
                g_x[n * 80 + 32 + w * 3 + c] = x;
            }
        } else {
            #pragma unroll
            for (int w = 0; w < 16; w++) xv[w] = 0.f;
        }
        #pragma unroll
        for (int w = 0; w < 16; w++) vsum[w] += xv[w] * xv[w];
    }
    #pragma unroll
    for (int w = 0; w < 16; w++) {
        float s = warpsum(vsum[w]);
        if (lane == 0) atomicAdd(&st[64 + w], s);
    }
    __syncthreads();
    if (tid < 80) atomicAdd(&g_stats[tid], st[tid]);
}

__global__ void k_stats(const float* __restrict__ bn_ws,
                        const float* __restrict__ bn_bs,
                        const float* __restrict__ bn_wv) {
    int i = threadIdx.x;
    if (i < 32) {
        float mean = g_stats[i] / (float)Nn;
        float var  = g_stats[32 + i] / (float)Nn - mean * mean;
        float sc   = bn_ws[i] / sqrtf(var + 1e-5f);
        g_norm[i]      = sc;
        g_norm[32 + i] = bn_bs[i] - mean * sc;
    } else if (i < 48) {
        int v = i - 32;
        float vn = g_stats[64 + v] / (3.f * (float)Nn);
        g_norm[64 + v] = bn_wv[v] / sqrtf(vn + 1e-5f);
    }
}

__global__ void k_out(float* __restrict__ out) {
    int idx = blockIdx.x * blockDim.x + threadIdx.x;
    if (idx >= Nn * 80) return;
    int f = idx % 80;
    float x = g_x[idx];
    if (f < 32) out[idx] = x * g_norm[f] + g_norm[32 + f];
    else        out[idx] = x * g_norm[64 + (f - 32) / 3];
}

extern "C" void kernel_launch(void* const* d_in, const int* in_sizes, int n_in,
                              void* d_out, int out_size) {
    const float* nf     = (const float*)d_in[0];
    const int*   ei     = (const int*)  d_in[1];
    const float* sh     = (const float*)d_in[2];
    const float* radial = (const float*)d_in[3];
    const float* env    = (const float*)d_in[4];
    const float* W1     = (const float*)d_in[5];
    const float* b1     = (const float*)d_in[6];
    const float* W2     = (const float*)d_in[7];
    const float* b2     = (const float*)d_in[8];
    const float* Wq     = (const float*)d_in[9];
    const float* bq     = (const float*)d_in[10];
    const float* Wk     = (const float*)d_in[11];
    const float* bk     = (const float*)d_in[12];
    const float* Wout_s = (const float*)d_in[13];
    const float* Wout_v = (const float*)d_in[14];
    const float* Wg_s   = (const float*)d_in[15];
    const float* Wg_v   = (const float*)d_in[16];
    const float* bn_ws  = (const float*)d_in[17];
    const float* bn_bs  = (const float*)d_in[18];
    const float* bn_wv  = (const float*)d_in[19];
    float* out = (float*)d_out;

    cudaFuncSetAttribute(k_edge, cudaFuncAttributeMaxDynamicSharedMemorySize, SMEM_BYTES);

    k_init<<<1024, 256>>>();
    k_prep<<<40, 256>>>(W2);
    k_edge<<<Ee / 32, 256, SMEM_BYTES>>>(nf, ei, sh, radial, env,
                                         W1, b1, b2, Wq, bq, Wk, bk);
    k_soft<<<(Ee + 255) / 256, 256>>>(ei);
    k_agg<<<(Ee * 80 + 255) / 256, 256>>>(ei);
    k_node<<<(Nn + 255) / 256, 256>>>(nf, Wout_s, Wout_v, Wg_s, Wg_v);
    k_stats<<<1, 64>>>(bn_ws, bn_bs, bn_wv);
    k_out<<<(Nn * 80 + 255) / 256, 256>>>(out);
}